// round 1
// baseline (speedup 1.0000x reference)
#include <cuda_runtime.h>
#include <math.h>

#define B_    8
#define T_    12
#define NN_   883
#define DM    152
#define DD2   304
#define SSZ   128
#define NL    3
#define STEPS 288
#define ROWS  (B_*NN_)        /* 7064  */
#define MTOK  (ROWS*T_)       /* 84768 */

// ---------------- scratch (device globals; no allocs allowed) ----------------
__device__ float g_h    [MTOK*DM];
__device__ float g_xn   [MTOK*DM];
__device__ float g_xp   [MTOK*DD2];   // also reused for x_comb
__device__ float g_xca  [MTOK*DD2];
__device__ float g_xco  [MTOK*DD2];
__device__ float g_delta[MTOK*DD2];
__device__ float g_z    [MTOK*DD2];
__device__ float g_Bm   [MTOK*SSZ];
__device__ float g_Cm   [MTOK*SSZ];
__device__ float g_s    [MTOK];

__device__ __forceinline__ float siluf(float v)     { return v / (1.f + expf(-v)); }
__device__ __forceinline__ float softplusf(float v) { return (v > 20.f) ? v : log1pf(expf(v)); }

// ---------------- embedding: build h (BN, T, 152) ----------------
__global__ void embed_kernel(const float* __restrict__ x, const float* __restrict__ W_in,
                             const float* __restrict__ b_in, const float* __restrict__ tod,
                             const float* __restrict__ dow, const float* __restrict__ adp)
{
    long idx = blockIdx.x * (long)blockDim.x + threadIdx.x;
    if (idx >= (long)MTOK * DM) return;
    int  c      = (int)(idx % DM);
    long tokidx = idx / DM;
    int  t      = (int)(tokidx % T_);
    long rn     = tokidx / T_;            // b*N + n
    int  n      = (int)(rn % NN_);
    int  b      = (int)(rn / NN_);
    const float* xe = x + (((long)(b * T_ + t) * NN_ + n) * 3);
    float v;
    if (c < 24) {
        v = b_in[c] + xe[0]*W_in[c] + xe[1]*W_in[24+c] + xe[2]*W_in[48+c];
    } else if (c < 48) {
        int ti = (int)(xe[1] * (float)STEPS);
        ti = min(max(ti, 0), STEPS - 1);
        v = tod[ti*24 + (c-24)];
    } else if (c < 72) {
        int di = (int)xe[2];
        di = min(max(di, 0), 6);
        v = dow[di*24 + (c-48)];
    } else {
        v = adp[((long)t * NN_ + n) * 80 + (c - 72)];
    }
    g_h[idx] = v;
}

// ---------------- rmsnorm (one warp per token row of 152) ----------------
__global__ void rmsnorm_kernel(const float* __restrict__ w)
{
    int gwarp = (blockIdx.x * blockDim.x + threadIdx.x) >> 5;
    int lane  = threadIdx.x & 31;
    if (gwarp >= MTOK) return;
    const float* row = g_h + (long)gwarp * DM;
    float ss = 0.f;
    for (int c = lane; c < DM; c += 32) { float v = row[c]; ss += v * v; }
    #pragma unroll
    for (int o = 16; o; o >>= 1) ss += __shfl_xor_sync(0xffffffffu, ss, o);
    float scale = rsqrtf(ss / (float)DM + 1e-5f);
    float* orow = g_xn + (long)gwarp * DM;
    for (int c = lane; c < DM; c += 32) orow[c] = row[c] * scale * w[c];
}

// ---------------- SGEMM 128x128x8, 8x8 per thread, fused epilogue ----------------
// EPI: 0 = bias, 1 = silu(bias+acc), 2 = softplus(bias+acc)
template<int EPI>
__global__ void __launch_bounds__(256, 2)
gemm_kernel(const float* __restrict__ A, const float* __restrict__ W,
            const float* __restrict__ bias, float* __restrict__ C,
            int M, int K, int N)
{
    __shared__ float As[8][128];
    __shared__ float Ws[8][128];

    int tid = threadIdx.x;
    int tx  = tid & 15, ty = tid >> 4;
    int m0  = blockIdx.y * 128, n0 = blockIdx.x * 128;

    float acc[8][8];
    #pragma unroll
    for (int i = 0; i < 8; i++)
        #pragma unroll
        for (int j = 0; j < 8; j++) acc[i][j] = 0.f;

    int arow = tid >> 1, acol = (tid & 1) * 4;   // A tile: 128 x 8
    int krow = tid >> 5, wcol = (tid & 31) * 4;  // W tile: 8 x 128

    for (int k0 = 0; k0 < K; k0 += 8) {
        float4 av = make_float4(0.f, 0.f, 0.f, 0.f);
        int grow = m0 + arow;
        if (grow < M) av = *(const float4*)(A + (long)grow * K + k0 + acol);
        As[acol+0][arow] = av.x; As[acol+1][arow] = av.y;
        As[acol+2][arow] = av.z; As[acol+3][arow] = av.w;

        float4 wv = make_float4(0.f, 0.f, 0.f, 0.f);
        if (n0 + wcol < N) wv = *(const float4*)(W + (long)(k0 + krow) * N + n0 + wcol);
        *(float4*)&Ws[krow][wcol] = wv;

        __syncthreads();
        #pragma unroll
        for (int k = 0; k < 8; k++) {
            float af[8], wf[8];
            *(float4*)&af[0] = *(const float4*)&As[k][ty*8];
            *(float4*)&af[4] = *(const float4*)&As[k][ty*8+4];
            *(float4*)&wf[0] = *(const float4*)&Ws[k][tx*8];
            *(float4*)&wf[4] = *(const float4*)&Ws[k][tx*8+4];
            #pragma unroll
            for (int i = 0; i < 8; i++)
                #pragma unroll
                for (int j = 0; j < 8; j++)
                    acc[i][j] = fmaf(af[i], wf[j], acc[i][j]);
        }
        __syncthreads();
    }

    #pragma unroll
    for (int i = 0; i < 8; i++) {
        int row = m0 + ty * 8 + i;
        if (row >= M) continue;
        #pragma unroll
        for (int j = 0; j < 8; j++) {
            int col = n0 + tx * 8 + j;
            if (col >= N) continue;
            float v = acc[i][j] + bias[col];
            if (EPI == 1) v = siluf(v);
            if (EPI == 2) v = softplusf(v);
            C[(long)row * N + col] = v;
        }
    }
}

// ---------------- conv over T (channels=T, spatial=D2, k=3, pad=1) + silu ----------------
__global__ void conv_silu_kernel(const float* __restrict__ cw, const float* __restrict__ cb)
{
    __shared__ float w[T_*T_*3];
    __shared__ float bsh[T_];
    for (int i = threadIdx.x; i < T_*T_*3; i += blockDim.x) w[i] = cw[i];
    for (int i = threadIdx.x; i < T_;      i += blockDim.x) bsh[i] = cb[i];
    __syncthreads();

    long idx = blockIdx.x * (long)blockDim.x + threadIdx.x;
    if (idx >= (long)ROWS * DD2) return;
    int  d = (int)(idx % DD2);
    long r = idx / DD2;
    const float* xrow = g_xp + r * (long)(T_ * DD2);

    float acc[T_];
    #pragma unroll
    for (int to = 0; to < T_; to++) acc[to] = bsh[to];

    #pragma unroll
    for (int ti = 0; ti < T_; ti++) {
        float v0 = (d > 0)       ? xrow[ti*DD2 + d - 1] : 0.f;
        float v1 =                 xrow[ti*DD2 + d];
        float v2 = (d < DD2 - 1) ? xrow[ti*DD2 + d + 1] : 0.f;
        #pragma unroll
        for (int to = 0; to < T_; to++) {
            const float* wp = &w[(to*T_ + ti)*3];
            acc[to] += v0*wp[0] + v1*wp[1] + v2*wp[2];
        }
    }
    float* orow = g_xca + r * (long)(T_ * DD2);
    #pragma unroll
    for (int to = 0; to < T_; to++) orow[to*DD2 + d] = siluf(acc[to]);
}

// ---------------- s[token] = dot(Bm, Cm) over 128 (warp per token) ----------------
__global__ void sdot_kernel()
{
    int gwarp = (blockIdx.x * blockDim.x + threadIdx.x) >> 5;
    int lane  = threadIdx.x & 31;
    if (gwarp >= MTOK) return;
    const float* b = g_Bm + (long)gwarp * SSZ;
    const float* c = g_Cm + (long)gwarp * SSZ;
    float acc = 0.f;
    #pragma unroll
    for (int i = lane; i < SSZ; i += 32) acc += b[i] * c[i];
    #pragma unroll
    for (int o = 16; o; o >>= 1) acc += __shfl_xor_sync(0xffffffffu, acc, o);
    if (!lane) g_s[gwarp] = acc;
}

// ---------------- x_comb = silu(xco*delta*s) * silu_z  (silu_z precomputed in g_z) ----------------
__global__ void combine_kernel()
{
    long idx = blockIdx.x * (long)blockDim.x + threadIdx.x;
    if (idx >= (long)MTOK * DD2) return;
    long tok = idx / DD2;
    float y = g_xco[idx] * g_delta[idx] * g_s[tok];
    g_xp[idx] = siluf(y) * g_z[idx];
}

// ---------------- head: (B,N) rows of 1824 @ W_out(1824,12); 12 warps/block ----------------
__global__ void out_kernel(const float* __restrict__ Wout, const float* __restrict__ bout,
                           float* __restrict__ out)
{
    int rn   = blockIdx.x;          // b*N + n
    int wj   = threadIdx.x >> 5;    // 0..11 output index
    int lane = threadIdx.x & 31;
    const float* row = g_h + (long)rn * (T_ * DM);
    float acc = 0.f;
    for (int k = lane; k < T_ * DM; k += 32) acc += row[k] * Wout[k*12 + wj];
    #pragma unroll
    for (int o = 16; o; o >>= 1) acc += __shfl_xor_sync(0xffffffffu, acc, o);
    if (!lane) {
        int n = rn % NN_, b = rn / NN_;
        out[((long)b * 12 + wj) * NN_ + n] = acc + bout[wj];
    }
}

// =============================================================================
extern "C" void kernel_launch(void* const* d_in, const int* in_sizes, int n_in,
                              void* d_out, int out_size)
{
    (void)in_sizes; (void)n_in; (void)out_size;
    const float* x        = (const float*)d_in[0];
    const float* W_in     = (const float*)d_in[1];
    const float* b_in     = (const float*)d_in[2];
    const float* tod      = (const float*)d_in[3];
    const float* dow      = (const float*)d_in[4];
    const float* adp      = (const float*)d_in[5];
    const float* norm_w   = (const float*)d_in[6];
    const float* inproj_w = (const float*)d_in[7];
    const float* inproj_b = (const float*)d_in[8];
    const float* conv_w   = (const float*)d_in[9];
    const float* conv_b   = (const float*)d_in[10];
    const float* convlin_w= (const float*)d_in[11];
    const float* convlin_b= (const float*)d_in[12];
    const float* fc1_w    = (const float*)d_in[13];
    const float* fc1_b    = (const float*)d_in[14];
    const float* fc2_w    = (const float*)d_in[15];
    const float* fc2_b    = (const float*)d_in[16];
    const float* fc3_w    = (const float*)d_in[17];
    const float* fc3_b    = (const float*)d_in[18];
    /* d_in[19] = A_ssm : unused (h0 == 0 => dA term vanishes) */
    const float* D_w      = (const float*)d_in[20];
    const float* D_b      = (const float*)d_in[21];
    const float* outproj_w= (const float*)d_in[22];
    const float* outproj_b= (const float*)d_in[23];
    const float* W_out    = (const float*)d_in[24];
    const float* b_out    = (const float*)d_in[25];
    float* out = (float*)d_out;

    void* p;
    cudaGetSymbolAddress(&p, g_xn);    float* xn_p    = (float*)p;
    cudaGetSymbolAddress(&p, g_xp);    float* xp_p    = (float*)p;
    cudaGetSymbolAddress(&p, g_xca);   float* xca_p   = (float*)p;
    cudaGetSymbolAddress(&p, g_xco);   float* xco_p   = (float*)p;
    cudaGetSymbolAddress(&p, g_delta); float* delta_p = (float*)p;
    cudaGetSymbolAddress(&p, g_z);     float* z_p     = (float*)p;
    cudaGetSymbolAddress(&p, g_Bm);    float* Bm_p    = (float*)p;
    cudaGetSymbolAddress(&p, g_Cm);    float* Cm_p    = (float*)p;
    cudaGetSymbolAddress(&p, g_h);     float* h_p     = (float*)p;

    const int MB = (MTOK + 127) / 128;      // 663 M-tiles

    {   // embedding
        long tot = (long)MTOK * DM;
        int  blk = (int)((tot + 255) / 256);
        embed_kernel<<<blk, 256>>>(x, W_in, b_in, tod, dow, adp);
    }

    for (int i = 0; i < NL; i++) {
        // rmsnorm: h -> xn
        rmsnorm_kernel<<<(MTOK * 32 + 255) / 256, 256>>>(norm_w + i * DM);

        // xn @ inproj + b -> xp
        gemm_kernel<0><<<dim3(3, MB), 256>>>(xn_p, inproj_w + (long)i*DM*DD2,
                                             inproj_b + i*DD2, xp_p, MTOK, DM, DD2);
        // conv over T + silu: xp -> xca
        conv_silu_kernel<<<((long)ROWS*DD2 + 255) / 256, 256>>>(conv_w + i*T_*T_*3,
                                                                conv_b + i*T_);
        // xca @ convlin + b -> xco
        gemm_kernel<0><<<dim3(3, MB), 256>>>(xca_p, convlin_w + (long)i*DD2*DD2,
                                             convlin_b + i*DD2, xco_p, MTOK, DD2, DD2);
        // Bm, Cm
        gemm_kernel<0><<<dim3(1, MB), 256>>>(xco_p, fc2_w + (long)i*DD2*SSZ,
                                             fc2_b + i*SSZ, Bm_p, MTOK, DD2, SSZ);
        gemm_kernel<0><<<dim3(1, MB), 256>>>(xco_p, fc3_w + (long)i*DD2*SSZ,
                                             fc3_b + i*SSZ, Cm_p, MTOK, DD2, SSZ);
        sdot_kernel<<<(MTOK * 32 + 255) / 256, 256>>>();
        // delta = softplus(xco @ fc1 + b)
        gemm_kernel<2><<<dim3(3, MB), 256>>>(xco_p, fc1_w + (long)i*DD2*DD2,
                                             fc1_b + i*DD2, delta_p, MTOK, DD2, DD2);
        // z = silu(xn @ D_w + D_b)
        gemm_kernel<1><<<dim3(3, MB), 256>>>(xn_p, D_w + (long)i*DM*DD2,
                                             D_b + i*DD2, z_p, MTOK, DM, DD2);
        // x_comb -> g_xp
        combine_kernel<<<((long)MTOK*DD2 + 255) / 256, 256>>>();
        // h = x_comb @ outproj + b
        gemm_kernel<0><<<dim3(2, MB), 256>>>(xp_p, outproj_w + (long)i*DD2*DM,
                                             outproj_b + i*DM, h_p, MTOK, DD2, DM);
    }

    out_kernel<<<ROWS, 384>>>(W_out, b_out, out);
}

// round 3
// speedup vs baseline: 2.4990x; 2.4990x over previous
#include <cuda_runtime.h>
#include <cuda_bf16.h>
#include <math.h>
#include <stdint.h>

#define B_    8
#define T_    12
#define NN_   883
#define DM    152
#define DD2   304
#define SSZ   128
#define NL    3
#define STEPS 288
#define ROWS  (B_*NN_)          /* 7064  */
#define MTOK  (ROWS*T_)         /* 84768 */
#define MTILES ((MTOK+127)/128) /* 663   */

// ---------------- scratch (device globals; no allocs allowed) ----------------
__device__ float g_h [MTOK*DM];
__device__ float g_xp[MTOK*DD2];
__device__ float g_BC[MTOK*256];
__device__ float g_z [MTOK*DD2];
__device__ float g_s [MTOK];

__device__ __nv_bfloat16 g_xn_h [MTOK*DM],  g_xn_l [MTOK*DM];
__device__ __nv_bfloat16 g_xca_h[MTOK*DD2], g_xca_l[MTOK*DD2];
__device__ __nv_bfloat16 g_xco_h[MTOK*DD2], g_xco_l[MTOK*DD2];
__device__ __nv_bfloat16 g_cb_h [MTOK*DD2], g_cb_l [MTOK*DD2];

// split + transposed weights: [N rows, K cols] bf16
__device__ __nv_bfloat16 g_wip_h[NL*DD2*DM],  g_wip_l[NL*DD2*DM];
__device__ __nv_bfloat16 g_wcl_h[NL*DD2*DD2], g_wcl_l[NL*DD2*DD2];
__device__ __nv_bfloat16 g_w23_h[NL*256*DD2], g_w23_l[NL*256*DD2];
__device__ __nv_bfloat16 g_wf1_h[NL*DD2*DD2], g_wf1_l[NL*DD2*DD2];
__device__ __nv_bfloat16 g_wdw_h[NL*DD2*DM],  g_wdw_l[NL*DD2*DM];
__device__ __nv_bfloat16 g_wop_h[NL*DM*DD2],  g_wop_l[NL*DM*DD2];
__device__ float g_b23[NL*256];

__device__ __forceinline__ float siluf(float v)     { return v / (1.f + expf(-v)); }
__device__ __forceinline__ float softplusf(float v) { return (v > 20.f) ? v : log1pf(expf(v)); }

__device__ __forceinline__ uint32_t sm2u32(const void* p) {
    uint32_t a;
    asm("{ .reg .u64 t; cvta.to.shared.u64 t, %1; cvt.u32.u64 %0, t; }" : "=r"(a) : "l"(p));
    return a;
}
#define SWZ(o) ((uint32_t)(o) ^ ((((uint32_t)(o)) >> 3) & 0x70u))

__device__ __forceinline__ void ldsm4(uint32_t* r, uint32_t addr) {
    asm volatile("ldmatrix.sync.aligned.m8n8.x4.shared.b16 {%0,%1,%2,%3}, [%4];"
                 : "=r"(r[0]), "=r"(r[1]), "=r"(r[2]), "=r"(r[3]) : "r"(addr));
}
__device__ __forceinline__ void mma16816(float* c, const uint32_t* a, const uint32_t* b) {
    asm volatile("mma.sync.aligned.m16n8k16.row.col.f32.bf16.bf16.f32 "
                 "{%0,%1,%2,%3}, {%4,%5,%6,%7}, {%8,%9}, {%0,%1,%2,%3};"
                 : "+f"(c[0]), "+f"(c[1]), "+f"(c[2]), "+f"(c[3])
                 : "r"(a[0]), "r"(a[1]), "r"(a[2]), "r"(a[3]), "r"(b[0]), "r"(b[1]));
}

// ---------------- GEMM with fused epilogue -----------------------------------
// EPI: 0 bias->f32, 1 silu->f32, 3 bias->split bf16, 4 fc1+combine->split bf16
template<int EPI>
__device__ __forceinline__ void epi2(int m, int col, int ldc, float v0, float v1,
    const float* __restrict__ bias, float* Cf, __nv_bfloat16* Ch, __nv_bfloat16* Cl)
{
    v0 += bias[col]; v1 += bias[col + 1];
    if (EPI == 1) { v0 = siluf(v0); v1 = siluf(v1); }
    if (EPI == 4) {
        float sv = g_s[m];
        size_t off = (size_t)m * DD2 + col;
        float xc0 = __bfloat162float(g_xco_h[off])   + __bfloat162float(g_xco_l[off]);
        float xc1 = __bfloat162float(g_xco_h[off+1]) + __bfloat162float(g_xco_l[off+1]);
        v0 = siluf(xc0 * softplusf(v0) * sv) * g_z[off];
        v1 = siluf(xc1 * softplusf(v1) * sv) * g_z[off + 1];
    }
    if (EPI == 0 || EPI == 1) {
        *(float2*)(Cf + (size_t)m * ldc + col) = make_float2(v0, v1);
    } else {
        __nv_bfloat16 h0 = __float2bfloat16(v0), h1 = __float2bfloat16(v1);
        __nv_bfloat16 l0 = __float2bfloat16(v0 - __bfloat162float(h0));
        __nv_bfloat16 l1 = __float2bfloat16(v1 - __bfloat162float(h1));
        *(__nv_bfloat162*)(Ch + (size_t)m * ldc + col) = __halves2bfloat162(h0, h1);
        *(__nv_bfloat162*)(Cl + (size_t)m * ldc + col) = __halves2bfloat162(l0, l1);
    }
}

// C[M,Nw] = epi(A[M,K] @ B[Nw,K]^T + bias). 128x64 tile, K-chunk 64.
#define SA_H 0
#define SA_L 16384
#define SB_H 32768
#define SB_L 40960

template<int EPI>
__global__ void __launch_bounds__(256)
mma_gemm(const __nv_bfloat16* __restrict__ Ah, const __nv_bfloat16* __restrict__ Al,
         const __nv_bfloat16* __restrict__ Bh, const __nv_bfloat16* __restrict__ Bl,
         const float* __restrict__ bias,
         float* Cf, __nv_bfloat16* Ch, __nv_bfloat16* Cl,
         int M, int K, int Nw, int ldc)
{
    __shared__ __align__(1024) char smem[49152];
    const uint32_t sb = sm2u32(smem);
    const int tid  = threadIdx.x;
    const int lane = tid & 31;
    const int wid  = tid >> 5;
    const int wm   = wid & 3;      // 4 warps along M
    const int wn   = wid >> 2;     // 2 warps along N
    const int m0   = blockIdx.y * 128;
    const int n0   = blockIdx.x * 64;

    float acc[2][4][4];
#pragma unroll
    for (int i = 0; i < 2; i++)
#pragma unroll
        for (int j = 0; j < 4; j++)
#pragma unroll
            for (int q = 0; q < 4; q++) acc[i][j][q] = 0.f;

    for (int k0 = 0; k0 < K; k0 += 64) {
        // ---- load A chunk: 128 x 64 (hi & lo) ----
#pragma unroll
        for (int i = 0; i < 4; i++) {
            int seg = tid + i * 256;
            int r = seg >> 3, u = seg & 7;
            int gm = m0 + r, gk = k0 + u * 8;
            uint4 vh = make_uint4(0u,0u,0u,0u), vl = make_uint4(0u,0u,0u,0u);
            if (gm < M && gk < K) {
                vh = *(const uint4*)(Ah + (size_t)gm * K + gk);
                vl = *(const uint4*)(Al + (size_t)gm * K + gk);
            }
            uint32_t o = SWZ(r * 128 + u * 16);
            *(uint4*)(smem + SA_H + o) = vh;
            *(uint4*)(smem + SA_L + o) = vl;
        }
        // ---- load B chunk: 64 x 64 (hi & lo) ----
#pragma unroll
        for (int i = 0; i < 2; i++) {
            int seg = tid + i * 256;
            int r = seg >> 3, u = seg & 7;
            int gn = n0 + r, gk = k0 + u * 8;
            uint4 vh = make_uint4(0u,0u,0u,0u), vl = make_uint4(0u,0u,0u,0u);
            if (gn < Nw && gk < K) {
                vh = *(const uint4*)(Bh + (size_t)gn * K + gk);
                vl = *(const uint4*)(Bl + (size_t)gn * K + gk);
            }
            uint32_t o = SWZ(r * 128 + u * 16);
            *(uint4*)(smem + SB_H + o) = vh;
            *(uint4*)(smem + SB_L + o) = vl;
        }
        __syncthreads();

#pragma unroll
        for (int ks = 0; ks < 4; ks++) {
            const int kb = ks * 16;
            // A fragments (2 m-tiles, hi & lo)
            uint32_t ah[2][4], al[2][4];
#pragma unroll
            for (int mt = 0; mt < 2; mt++) {
                int row = wm * 32 + mt * 16 + (lane & 15);
                uint32_t ad = sb + SWZ(row * 128 + (kb + (lane >> 4) * 8) * 2);
                ldsm4(ah[mt], ad + SA_H);
                ldsm4(al[mt], ad + SA_L);
            }
            // B fragments (4 n-tiles via 2 x4 loads, hi & lo)
            uint32_t bh[4][2], bl[4][2];
            {
                int q = lane >> 3;
                int rowo = (q >> 1) * 8 + (lane & 7);
                int ko   = (q & 1) * 8;
#pragma unroll
                for (int p = 0; p < 2; p++) {
                    int row = wn * 32 + p * 16 + rowo;
                    uint32_t bd = sb + SWZ(row * 128 + (kb + ko) * 2);
                    uint32_t r4[4];
                    ldsm4(r4, bd + SB_H);
                    bh[p*2][0] = r4[0]; bh[p*2][1] = r4[1];
                    bh[p*2+1][0] = r4[2]; bh[p*2+1][1] = r4[3];
                    ldsm4(r4, bd + SB_L);
                    bl[p*2][0] = r4[0]; bl[p*2][1] = r4[1];
                    bl[p*2+1][0] = r4[2]; bl[p*2+1][1] = r4[3];
                }
            }
            // 3-term split products
#pragma unroll
            for (int mt = 0; mt < 2; mt++)
#pragma unroll
                for (int nt = 0; nt < 4; nt++) {
                    mma16816(acc[mt][nt], ah[mt], bh[nt]);
                    mma16816(acc[mt][nt], ah[mt], bl[nt]);
                    mma16816(acc[mt][nt], al[mt], bh[nt]);
                }
        }
        __syncthreads();
    }

    // ---- epilogue ----
#pragma unroll
    for (int mt = 0; mt < 2; mt++) {
        int r0 = m0 + wm * 32 + mt * 16 + (lane >> 2);
        int r1 = r0 + 8;
#pragma unroll
        for (int nt = 0; nt < 4; nt++) {
            int col = n0 + wn * 32 + nt * 8 + (lane & 3) * 2;
            if (col < Nw) {
                if (r0 < M) epi2<EPI>(r0, col, ldc, acc[mt][nt][0], acc[mt][nt][1], bias, Cf, Ch, Cl);
                if (r1 < M) epi2<EPI>(r1, col, ldc, acc[mt][nt][2], acc[mt][nt][3], bias, Cf, Ch, Cl);
            }
        }
    }
}

// ---------------- weight transpose + split: W[K,N] -> Bt[N,K] hi/lo ----------
__global__ void wsplit(const float* __restrict__ W, __nv_bfloat16* __restrict__ oh,
                       __nv_bfloat16* __restrict__ ol, int K, int N)
{
    int idx = blockIdx.x * blockDim.x + threadIdx.x;
    if (idx >= K * N) return;
    int n = idx / K, k = idx % K;
    float v = W[(size_t)k * N + n];
    __nv_bfloat16 h = __float2bfloat16(v);
    oh[idx] = h;
    ol[idx] = __float2bfloat16(v - __bfloat162float(h));
}

__global__ void pack_b23(const float* __restrict__ b2, const float* __restrict__ b3,
                         float* __restrict__ dst)
{
    int i = threadIdx.x;
    dst[i] = (i < 128) ? b2[i] : b3[i - 128];
}

// ---------------- embedding ----------------
__global__ void embed_kernel(const float* __restrict__ x, const float* __restrict__ W_in,
                             const float* __restrict__ b_in, const float* __restrict__ tod,
                             const float* __restrict__ dow, const float* __restrict__ adp)
{
    long idx = blockIdx.x * (long)blockDim.x + threadIdx.x;
    if (idx >= (long)MTOK * DM) return;
    int  c      = (int)(idx % DM);
    long tokidx = idx / DM;
    int  t      = (int)(tokidx % T_);
    long rn     = tokidx / T_;
    int  n      = (int)(rn % NN_);
    int  b      = (int)(rn / NN_);
    const float* xe = x + (((long)(b * T_ + t) * NN_ + n) * 3);
    float v;
    if (c < 24) {
        v = b_in[c] + xe[0]*W_in[c] + xe[1]*W_in[24+c] + xe[2]*W_in[48+c];
    } else if (c < 48) {
        int ti = (int)(xe[1] * (float)STEPS);
        ti = min(max(ti, 0), STEPS - 1);
        v = tod[ti*24 + (c-24)];
    } else if (c < 72) {
        int di = (int)xe[2];
        di = min(max(di, 0), 6);
        v = dow[di*24 + (c-48)];
    } else {
        v = adp[((long)t * NN_ + n) * 80 + (c - 72)];
    }
    g_h[idx] = v;
}

// ---------------- rmsnorm -> split bf16 ----------------
__global__ void rmsnorm_kernel(const float* __restrict__ w)
{
    int gwarp = (blockIdx.x * blockDim.x + threadIdx.x) >> 5;
    int lane  = threadIdx.x & 31;
    if (gwarp >= MTOK) return;
    const float* row = g_h + (long)gwarp * DM;
    float ss = 0.f;
    for (int c = lane; c < DM; c += 32) { float v = row[c]; ss += v * v; }
#pragma unroll
    for (int o = 16; o; o >>= 1) ss += __shfl_xor_sync(0xffffffffu, ss, o);
    float scale = rsqrtf(ss / (float)DM + 1e-5f);
    long base = (long)gwarp * DM;
    for (int c = lane; c < DM; c += 32) {
        float v = row[c] * scale * w[c];
        __nv_bfloat16 h = __float2bfloat16(v);
        g_xn_h[base + c] = h;
        g_xn_l[base + c] = __float2bfloat16(v - __bfloat162float(h));
    }
}

// ---------------- conv over T + silu -> split bf16 ----------------
__global__ void conv_silu_kernel(const float* __restrict__ cw, const float* __restrict__ cb)
{
    __shared__ float w[T_*T_*3];
    __shared__ float bsh[T_];
    for (int i = threadIdx.x; i < T_*T_*3; i += blockDim.x) w[i] = cw[i];
    for (int i = threadIdx.x; i < T_;      i += blockDim.x) bsh[i] = cb[i];
    __syncthreads();

    long idx = blockIdx.x * (long)blockDim.x + threadIdx.x;
    if (idx >= (long)ROWS * DD2) return;
    int  d = (int)(idx % DD2);
    long r = idx / DD2;
    const float* xrow = g_xp + r * (long)(T_ * DD2);

    float acc[T_];
#pragma unroll
    for (int to = 0; to < T_; to++) acc[to] = bsh[to];
#pragma unroll
    for (int ti = 0; ti < T_; ti++) {
        float v0 = (d > 0)       ? xrow[ti*DD2 + d - 1] : 0.f;
        float v1 =                 xrow[ti*DD2 + d];
        float v2 = (d < DD2 - 1) ? xrow[ti*DD2 + d + 1] : 0.f;
#pragma unroll
        for (int to = 0; to < T_; to++) {
            const float* wp = &w[(to*T_ + ti)*3];
            acc[to] += v0*wp[0] + v1*wp[1] + v2*wp[2];
        }
    }
    long obase = r * (long)(T_ * DD2) + d;
#pragma unroll
    for (int to = 0; to < T_; to++) {
        float v = siluf(acc[to]);
        __nv_bfloat16 h = __float2bfloat16(v);
        g_xca_h[obase + to*DD2] = h;
        g_xca_l[obase + to*DD2] = __float2bfloat16(v - __bfloat162float(h));
    }
}

// ---------------- s[token] = dot(BC[:,0:128], BC[:,128:256]) ----------------
__global__ void sdot_kernel()
{
    int gwarp = (blockIdx.x * blockDim.x + threadIdx.x) >> 5;
    int lane  = threadIdx.x & 31;
    if (gwarp >= MTOK) return;
    const float* row = g_BC + (long)gwarp * 256;
    float acc = 0.f;
#pragma unroll
    for (int i = lane; i < SSZ; i += 32) acc += row[i] * row[128 + i];
#pragma unroll
    for (int o = 16; o; o >>= 1) acc += __shfl_xor_sync(0xffffffffu, acc, o);
    if (!lane) g_s[gwarp] = acc;
}

// ---------------- head ----------------
__global__ void out_kernel(const float* __restrict__ Wout, const float* __restrict__ bout,
                           float* __restrict__ out)
{
    int rn   = blockIdx.x;
    int wj   = threadIdx.x >> 5;
    int lane = threadIdx.x & 31;
    const float* row = g_h + (long)rn * (T_ * DM);
    float acc = 0.f;
    for (int k = lane; k < T_ * DM; k += 32) acc += row[k] * Wout[k*12 + wj];
#pragma unroll
    for (int o = 16; o; o >>= 1) acc += __shfl_xor_sync(0xffffffffu, acc, o);
    if (!lane) {
        int n = rn % NN_, b = rn / NN_;
        out[((long)b * 12 + wj) * NN_ + n] = acc + bout[wj];
    }
}

// =============================================================================
extern "C" void kernel_launch(void* const* d_in, const int* in_sizes, int n_in,
                              void* d_out, int out_size)
{
    (void)in_sizes; (void)n_in; (void)out_size;
    const float* x        = (const float*)d_in[0];
    const float* W_in     = (const float*)d_in[1];
    const float* b_in     = (const float*)d_in[2];
    const float* tod      = (const float*)d_in[3];
    const float* dow      = (const float*)d_in[4];
    const float* adp      = (const float*)d_in[5];
    const float* norm_w   = (const float*)d_in[6];
    const float* inproj_w = (const float*)d_in[7];
    const float* inproj_b = (const float*)d_in[8];
    const float* conv_w   = (const float*)d_in[9];
    const float* conv_b   = (const float*)d_in[10];
    const float* convlin_w= (const float*)d_in[11];
    const float* convlin_b= (const float*)d_in[12];
    const float* fc1_w    = (const float*)d_in[13];
    const float* fc1_b    = (const float*)d_in[14];
    const float* fc2_w    = (const float*)d_in[15];
    const float* fc2_b    = (const float*)d_in[16];
    const float* fc3_w    = (const float*)d_in[17];
    const float* fc3_b    = (const float*)d_in[18];
    /* d_in[19] = A_ssm unused (h0 == 0) */
    const float* D_w      = (const float*)d_in[20];
    const float* D_b      = (const float*)d_in[21];
    const float* outproj_w= (const float*)d_in[22];
    const float* outproj_b= (const float*)d_in[23];
    const float* W_out    = (const float*)d_in[24];
    const float* b_out    = (const float*)d_in[25];
    float* out = (float*)d_out;

    void* p;
#define SYM(sym, var, ty) cudaGetSymbolAddress(&p, sym); ty* var = (ty*)p;
    SYM(g_xp,    xp_p,   float)
    SYM(g_BC,    BC_p,   float)
    SYM(g_z,     z_p,    float)
    SYM(g_b23,   b23_p,  float)
    SYM(g_h,     h_p,    float)
    SYM(g_xn_h,  xnh_p,  __nv_bfloat16)  SYM(g_xn_l,  xnl_p,  __nv_bfloat16)
    SYM(g_xca_h, xcah_p, __nv_bfloat16)  SYM(g_xca_l, xcal_p, __nv_bfloat16)
    SYM(g_xco_h, xcoh_p, __nv_bfloat16)  SYM(g_xco_l, xcol_p, __nv_bfloat16)
    SYM(g_cb_h,  cbh_p,  __nv_bfloat16)  SYM(g_cb_l,  cbl_p,  __nv_bfloat16)
    SYM(g_wip_h, wiph_p, __nv_bfloat16)  SYM(g_wip_l, wipl_p, __nv_bfloat16)
    SYM(g_wcl_h, wclh_p, __nv_bfloat16)  SYM(g_wcl_l, wcll_p, __nv_bfloat16)
    SYM(g_w23_h, w23h_p, __nv_bfloat16)  SYM(g_w23_l, w23l_p, __nv_bfloat16)
    SYM(g_wf1_h, wf1h_p, __nv_bfloat16)  SYM(g_wf1_l, wf1l_p, __nv_bfloat16)
    SYM(g_wdw_h, wdwh_p, __nv_bfloat16)  SYM(g_wdw_l, wdwl_p, __nv_bfloat16)
    SYM(g_wop_h, woph_p, __nv_bfloat16)  SYM(g_wop_l, wopl_p, __nv_bfloat16)
#undef SYM

    // ---- weight prep ----
    for (int i = 0; i < NL; i++) {
        wsplit<<<(DD2*DM + 255)/256, 256>>>(inproj_w + (long)i*DM*DD2,
            wiph_p + (long)i*DD2*DM, wipl_p + (long)i*DD2*DM, DM, DD2);
        wsplit<<<(DD2*DD2 + 255)/256, 256>>>(convlin_w + (long)i*DD2*DD2,
            wclh_p + (long)i*DD2*DD2, wcll_p + (long)i*DD2*DD2, DD2, DD2);
        wsplit<<<(SSZ*DD2 + 255)/256, 256>>>(fc2_w + (long)i*DD2*SSZ,
            w23h_p + (long)i*256*DD2,            w23l_p + (long)i*256*DD2, DD2, SSZ);
        wsplit<<<(SSZ*DD2 + 255)/256, 256>>>(fc3_w + (long)i*DD2*SSZ,
            w23h_p + (long)i*256*DD2 + 128*DD2,  w23l_p + (long)i*256*DD2 + 128*DD2, DD2, SSZ);
        wsplit<<<(DD2*DD2 + 255)/256, 256>>>(fc1_w + (long)i*DD2*DD2,
            wf1h_p + (long)i*DD2*DD2, wf1l_p + (long)i*DD2*DD2, DD2, DD2);
        wsplit<<<(DD2*DM + 255)/256, 256>>>(D_w + (long)i*DM*DD2,
            wdwh_p + (long)i*DD2*DM, wdwl_p + (long)i*DD2*DM, DM, DD2);
        wsplit<<<(DM*DD2 + 255)/256, 256>>>(outproj_w + (long)i*DD2*DM,
            woph_p + (long)i*DM*DD2, wopl_p + (long)i*DM*DD2, DD2, DM);
        pack_b23<<<1, 256>>>(fc2_b + i*SSZ, fc3_b + i*SSZ, b23_p + i*256);
    }

    // ---- embedding ----
    {
        long tot = (long)MTOK * DM;
        embed_kernel<<<(int)((tot + 255)/256), 256>>>(x, W_in, b_in, tod, dow, adp);
    }

    for (int i = 0; i < NL; i++) {
        rmsnorm_kernel<<<(MTOK*32 + 255)/256, 256>>>(norm_w + i*DM);

        // inproj: xn(152) -> xp(304) f32
        mma_gemm<0><<<dim3(5, MTILES), 256>>>(xnh_p, xnl_p,
            wiph_p + (long)i*DD2*DM, wipl_p + (long)i*DD2*DM, inproj_b + i*DD2,
            xp_p, nullptr, nullptr, MTOK, DM, DD2, DD2);

        conv_silu_kernel<<<((long)ROWS*DD2 + 255)/256, 256>>>(conv_w + i*T_*T_*3, conv_b + i*T_);

        // convlin: xca(304) -> xco split(304)
        mma_gemm<3><<<dim3(5, MTILES), 256>>>(xcah_p, xcal_p,
            wclh_p + (long)i*DD2*DD2, wcll_p + (long)i*DD2*DD2, convlin_b + i*DD2,
            nullptr, xcoh_p, xcol_p, MTOK, DD2, DD2, DD2);

        // fc2|fc3 fused: xco(304) -> BC(256) f32
        mma_gemm<0><<<dim3(4, MTILES), 256>>>(xcoh_p, xcol_p,
            w23h_p + (long)i*256*DD2, w23l_p + (long)i*256*DD2, b23_p + i*256,
            BC_p, nullptr, nullptr, MTOK, DD2, 256, 256);

        sdot_kernel<<<(MTOK*32 + 255)/256, 256>>>();

        // z = silu(xn @ D_w + D_b)
        mma_gemm<1><<<dim3(5, MTILES), 256>>>(xnh_p, xnl_p,
            wdwh_p + (long)i*DD2*DM, wdwl_p + (long)i*DD2*DM, D_b + i*DD2,
            z_p, nullptr, nullptr, MTOK, DM, DD2, DD2);

        // fc1 + combine fused: -> cb split(304)
        mma_gemm<4><<<dim3(5, MTILES), 256>>>(xcoh_p, xcol_p,
            wf1h_p + (long)i*DD2*DD2, wf1l_p + (long)i*DD2*DD2, fc1_b + i*DD2,
            nullptr, cbh_p, cbl_p, MTOK, DD2, DD2, DD2);

        // outproj: cb(304) -> h(152) f32
        mma_gemm<0><<<dim3(3, MTILES), 256>>>(cbh_p, cbl_p,
            woph_p + (long)i*DM*DD2, wopl_p + (long)i*DM*DD2, outproj_b + i*DM,
            h_p, nullptr, nullptr, MTOK, DD2, DM, DM);
    }

    out_kernel<<<ROWS, 384>>>(W_out, b_out, out);
}